// round 15
// baseline (speedup 1.0000x reference)
#include <cuda_runtime.h>
#include <cstdint>

// ---------------- problem constants (fixed by setup_inputs) ----------------
#define N_NODES 8192
#define DIMS    128
#define KSEL    4096          // N * RATIO
#define NEDGE   8192          // E == N
#define NKEEP   (N_NODES - KSEL)
#define EPSN    1e-12f

// output layout (float32), reference-return order flattened
#define OFF_X     0
#define OFF_EI    (KSEL * DIMS)            // 524288
#define OFF_EJ    (OFF_EI + NKEEP)         // 528384
#define OFF_PERM  (OFF_EJ + NKEEP)         // 532480
#define OFF_BATCH (OFF_PERM + KSEL)        // 536576
#define OFF_W     (OFF_BATCH + KSEL)       // 540672  (total 544768)

// ---------------- device scratch (static, no allocations) ----------------
__device__ float              g_xn[N_NODES * DIMS];   // normalized features (4 MB)
__device__ int                g_deg[N_NODES];
__device__ unsigned int       g_ekeys[NEDGE];         // (src<<13)|dst, sorted asc
__device__ float              g_term[NEDGE];          // per-sorted-edge weight term
__device__ float              g_w[N_NODES];
__device__ int                g_perm[KSEL];
__device__ int                g_newid[N_NODES];
__device__ int                g_sel[N_NODES];
__device__ int                g_segstart[N_NODES];
__device__ int                g_segend[N_NODES];

// ---------------- error-free f32 helpers (FMA pipe only) ----------------
__device__ __forceinline__ void two_sum(float a, float b, float& s, float& e) {
    s = a + b;
    float bp = s - a;
    e = (a - (s - bp)) + (b - bp);
}
__device__ __forceinline__ void acc_prod(float a, float b, float& s, float& c) {
    float p = a * b;
    float e = fmaf(a, b, -p);        // exact product error
    float t, err;
    two_sum(s, p, t, err);
    s = t; c += e + err;
}
__device__ __forceinline__ void merge_sc(float s2, float c2, float& s, float& c) {
    float t, err;
    two_sum(s, s2, t, err);
    s = t; c += c2 + err;
}

// ---------------- L1: norms + clears (blocks 0..255) | edge sort (block 256) --
// Norm path: warp per row, blocks 0..255 x 32 warps = 8192 warps.
// Sort block: single-block bitonic (R8-proven strided network) over 8192 u32
// keys in 32KB smem, then deg (unique edges) + per-src segment bounds.
// No cross-block hazards: sort block owns g_deg/g_segstart/g_segend/g_ekeys;
// norm blocks own g_xn/g_sel/g_newid.
__global__ void k_init_sort(const float* __restrict__ x, const int* __restrict__ ei) {
    __shared__ unsigned int sk[NEDGE];                 // 32 KB (used by block 256)
    int b = blockIdx.x;
    if (b < 256) {
        int t = b * 1024 + threadIdx.x;                // 0..262143
        if (t < N_NODES) { g_sel[t] = 0; g_newid[t] = 0; }
        int w = t >> 5;                                // 0..8191
        int lane = threadIdx.x & 31;
        float4 v = ((const float4*)(x + (size_t)w * DIMS))[lane];
        float s = 0.0f, c = 0.0f;
        acc_prod(v.x, v.x, s, c); acc_prod(v.y, v.y, s, c);
        acc_prod(v.z, v.z, s, c); acc_prod(v.w, v.w, s, c);
        #pragma unroll
        for (int o = 16; o; o >>= 1) {
            float s2 = __shfl_xor_sync(0xFFFFFFFFu, s, o);
            float c2 = __shfl_xor_sync(0xFFFFFFFFu, c, o);
            merge_sc(s2, c2, s, c);
        }
        float nf = fmaxf((float)sqrt((double)s + (double)c), EPSN);
        float4 xn;
        xn.x = v.x / nf; xn.y = v.y / nf; xn.z = v.z / nf; xn.w = v.w / nf;
        ((float4*)(g_xn + (size_t)w * DIMS))[lane] = xn;
    } else {
        int tid = threadIdx.x;
        for (int p = tid; p < NEDGE; p += 1024)
            sk[p] = ((unsigned int)ei[p] << 13) | (unsigned int)ei[NEDGE + p];
        for (int i = tid; i < N_NODES; i += 1024) {
            g_deg[i] = 0; g_segstart[i] = -1; g_segend[i] = 0;
        }
        __syncthreads();
        for (int k = 2; k <= NEDGE; k <<= 1) {
            for (int j = k >> 1; j > 0; j >>= 1) {
                for (int p = tid; p < NEDGE; p += 1024) {
                    int q = p ^ j;
                    if (q > p) {
                        unsigned int a = sk[p], bb = sk[q];
                        bool up = ((p & k) == 0);
                        if ((a > bb) == up) { sk[p] = bb; sk[q] = a; }
                    }
                }
                __syncthreads();
            }
        }
        for (int p = tid; p < NEDGE; p += 1024) {
            unsigned int key = sk[p];
            int src = (int)(key >> 13);
            g_ekeys[p] = key;
            if (p == 0 || (int)(sk[p - 1] >> 13) != src) g_segstart[src] = p;
            if (p == NEDGE - 1 || (int)(sk[p + 1] >> 13) != src) g_segend[src] = p + 1;
            if (p == 0 || sk[p - 1] != key) atomicAdd(&g_deg[src], 1);
        }
    }
}

// ---------------- L2: per-sorted-edge weight term (warp per edge) ------------
// Compensated f32 dot of normalized rows rounded once via double;
// term = (dis_i * sim) * dis_j (reference multiply order). Duplicates -> +0.0f.
__global__ void k_term() {
    int p = (blockIdx.x * blockDim.x + threadIdx.x) >> 5;
    int lane = threadIdx.x & 31;
    unsigned int key = g_ekeys[p];
    if (p > 0 && g_ekeys[p - 1] == key) {            // duplicate (warp-uniform)
        if (lane == 0) g_term[p] = 0.0f;
        return;
    }
    int i = (int)(key >> 13);
    int j = (int)(key & 8191u);
    float4 a = ((const float4*)(g_xn + (size_t)i * DIMS))[lane];
    float4 b = ((const float4*)(g_xn + (size_t)j * DIMS))[lane];
    float s = 0.0f, c = 0.0f;
    acc_prod(a.x, b.x, s, c); acc_prod(a.y, b.y, s, c);
    acc_prod(a.z, b.z, s, c); acc_prod(a.w, b.w, s, c);
    #pragma unroll
    for (int o = 16; o; o >>= 1) {
        float s2 = __shfl_xor_sync(0xFFFFFFFFu, s, o);
        float c2 = __shfl_xor_sync(0xFFFFFFFFu, c, o);
        merge_sc(s2, c2, s, c);
    }
    if (lane == 0) {
        float sim = (float)((double)s + (double)c);
        int dj = g_deg[j];
        float disi = (float)(1.0 / sqrt((double)g_deg[i]));
        float disj = (dj > 0) ? (float)(1.0 / sqrt((double)dj)) : 0.0f;
        g_term[p] = (disi * sim) * disj;
    }
}

// ---------------- L3: weights -> rank keys -> u64 sort -> permout ------------
// Single block, 1024 threads, 64KB dynamic smem. Per-node weight = sequential
// f32 sum over its sorted segment (ascending j = reference sum order). Rank
// key inverted so ascending sort == weight desc, index asc (lax.top_k ties).
__global__ void k_wsort(const int* __restrict__ batch, float* __restrict__ out) {
    extern __shared__ unsigned long long sw[];       // 64 KB
    int tid = threadIdx.x;
    for (int i = tid; i < N_NODES; i += 1024) {
        float acc = 0.0f;
        int s0 = g_segstart[i];
        if (s0 >= 0) {
            int s1 = g_segend[i];
            for (int p = s0; p < s1; p++) acc += g_term[p];
        }
        g_w[i] = acc;
        unsigned int u = __float_as_uint(acc);
        u = (u & 0x80000000u) ? ~u : (u | 0x80000000u);   // monotone map
        sw[i] = ~(((unsigned long long)u << 32) | (unsigned int)(N_NODES - 1 - i));
    }
    __syncthreads();
    for (int k = 2; k <= N_NODES; k <<= 1) {
        for (int j = k >> 1; j > 0; j >>= 1) {
            for (int p = tid; p < N_NODES; p += 1024) {
                int q = p ^ j;
                if (q > p) {
                    unsigned long long a = sw[p], b = sw[q];
                    bool up = ((p & k) == 0);
                    if ((a > b) == up) { sw[p] = b; sw[q] = a; }
                }
            }
            __syncthreads();
        }
    }
    for (int k = tid; k < KSEL; k += 1024) {
        unsigned long long key = ~sw[k];             // undo inversion
        int idx = (N_NODES - 1) - (int)(unsigned int)(key & 0xFFFFFFFFu);
        g_perm[k] = idx;
        g_sel[idx] = 1;
        g_newid[idx] = k;
        out[OFF_PERM + k]  = (float)idx;
        out[OFF_BATCH + k] = (float)batch[idx];
        out[OFF_W + k]     = g_w[idx];
    }
}

// ---------------- L4: x_pool gather (blocks 0..511) | keep (block 512) -------
__global__ void k_out(const float* __restrict__ x, const int* __restrict__ ei,
                      float* __restrict__ out) {
    __shared__ int s_off[1024];
    if (blockIdx.x < 512) {
        int t = blockIdx.x * 1024 + threadIdx.x;     // 0..524287
        int k = t >> 7, d = t & 127;
        out[OFF_X + t] = x[(size_t)g_perm[k] * DIMS + d];
    } else {
        int tid = threadIdx.x;
        int base = tid * 8;
        int c = 0;
        #pragma unroll
        for (int r = 0; r < 8; r++) c += (g_sel[base + r] == 0);
        s_off[tid] = c;
        __syncthreads();
        for (int o = 1; o < 1024; o <<= 1) {
            int v = s_off[tid];
            int u = (tid >= o) ? s_off[tid - o] : 0;
            __syncthreads();
            s_off[tid] = v + u;
            __syncthreads();
        }
        int off = s_off[tid] - c;                    // exclusive prefix
        for (int r = 0; r < 8; r++) {
            int node = base + r;
            if (!g_sel[node]) {
                out[OFF_EI + off] = (float)g_newid[ei[node]];
                out[OFF_EJ + off] = (float)g_newid[ei[NEDGE + node]];
                off++;
            }
        }
    }
}

// ---------------- launch ----------------
extern "C" void kernel_launch(void* const* d_in, const int* in_sizes, int n_in,
                              void* d_out, int out_size) {
    const float* x     = (const float*)d_in[0];
    const int*   ei    = (const int*)d_in[1];     // int32 (confirmed round 5)
    const int*   batch = (const int*)d_in[2];
    float* out = (float*)d_out;

    cudaFuncSetAttribute(k_wsort, cudaFuncAttributeMaxDynamicSharedMemorySize,
                         N_NODES * (int)sizeof(unsigned long long));

    k_init_sort<<<257, 1024>>>(x, ei);    // norms + clears | edge sort + deg + segs
    k_term     <<<1024, 256>>>();         // warp per sorted edge
    k_wsort    <<<1, 1024, N_NODES * (int)sizeof(unsigned long long)>>>(batch, out);
    k_out      <<<513, 1024>>>(x, ei, out);
}

// round 16
// speedup vs baseline: 2.0908x; 2.0908x over previous
#include <cuda_runtime.h>
#include <cstdint>

// ---------------- problem constants (fixed by setup_inputs) ----------------
#define N_NODES 8192
#define DIMS    128
#define KSEL    4096          // N * RATIO
#define NEDGE   8192          // E == N
#define NKEEP   (N_NODES - KSEL)
#define EPSN    1e-12f
#define TILE    2048          // bitonic block tile (4 blocks cover 8192)

// output layout (float32), reference-return order flattened
#define OFF_X     0
#define OFF_EI    (KSEL * DIMS)            // 524288
#define OFF_EJ    (OFF_EI + NKEEP)         // 528384
#define OFF_PERM  (OFF_EJ + NKEEP)         // 532480
#define OFF_BATCH (OFF_PERM + KSEL)        // 536576
#define OFF_W     (OFF_BATCH + KSEL)       // 540672  (total 544768)

// ---------------- device scratch (static, no allocations) ----------------
__device__ float              g_xn[N_NODES * DIMS];   // normalized features (4 MB)
__device__ int                g_count[N_NODES];       // per-src histogram (zeroed by k_scan)
__device__ int                g_cursor[N_NODES];      // scatter cursors
__device__ int                g_deg[N_NODES];
__device__ unsigned int       g_ekeys[NEDGE];         // (src<<13)|dst, segment-sorted
__device__ float              g_term[NEDGE];          // per-position weight term
__device__ float              g_w[N_NODES];
__device__ unsigned long long g_keys[N_NODES];        // ~rankkey, sorted asc
__device__ int                g_perm[KSEL];
__device__ int                g_newid[N_NODES];
__device__ int                g_sel[N_NODES];
__device__ int                g_segstart[N_NODES];
__device__ int                g_segend[N_NODES];

// ---------------- error-free f32 helpers (FMA pipe only) ----------------
__device__ __forceinline__ void two_sum(float a, float b, float& s, float& e) {
    s = a + b;
    float bp = s - a;
    e = (a - (s - bp)) + (b - bp);
}
__device__ __forceinline__ void acc_prod(float a, float b, float& s, float& c) {
    float p = a * b;
    float e = fmaf(a, b, -p);        // exact product error
    float t, err;
    two_sum(s, p, t, err);
    s = t; c += e + err;
}
__device__ __forceinline__ void merge_sc(float s2, float c2, float& s, float& c) {
    float t, err;
    two_sum(s, s2, t, err);
    s = t; c += c2 + err;
}

// ---------------- L1: norms + clears + edge histogram (256 x 1024) -----------
// Warp per row (8192 warps). Threads t<8192 also clear per-node scratch and
// histogram edge sources. g_count starts zero (module init) and is re-zeroed
// by k_scan each launch, so the atomicAdd histogram is replay-safe.
__global__ void k_init(const float* __restrict__ x, const int* __restrict__ ei) {
    int t = blockIdx.x * blockDim.x + threadIdx.x;
    if (t < N_NODES) {
        g_sel[t] = 0; g_newid[t] = 0;
        atomicAdd(&g_count[ei[t]], 1);
    }
    int w = t >> 5;
    int lane = threadIdx.x & 31;
    float4 v = ((const float4*)(x + (size_t)w * DIMS))[lane];
    float s = 0.0f, c = 0.0f;
    acc_prod(v.x, v.x, s, c); acc_prod(v.y, v.y, s, c);
    acc_prod(v.z, v.z, s, c); acc_prod(v.w, v.w, s, c);
    #pragma unroll
    for (int o = 16; o; o >>= 1) {
        float s2 = __shfl_xor_sync(0xFFFFFFFFu, s, o);
        float c2 = __shfl_xor_sync(0xFFFFFFFFu, c, o);
        merge_sc(s2, c2, s, c);
    }
    float nf = fmaxf((float)sqrt((double)s + (double)c), EPSN);
    float4 xn;
    xn.x = v.x / nf; xn.y = v.y / nf; xn.z = v.z / nf; xn.w = v.w / nf;
    ((float4*)(g_xn + (size_t)w * DIMS))[lane] = xn;
}

// ---------------- L2: exclusive scan of histogram (1 x 1024) -----------------
// segstart/segend/cursor per node; re-zeroes g_count for the next replay.
__global__ void k_scan() {
    __shared__ int sb[1024];
    int tid = threadIdx.x;
    int base = tid * 8;
    int c[8]; int sum = 0;
    #pragma unroll
    for (int r = 0; r < 8; r++) { c[r] = g_count[base + r]; sum += c[r]; }
    sb[tid] = sum;
    __syncthreads();
    for (int o = 1; o < 1024; o <<= 1) {
        int v = sb[tid];
        int u = (tid >= o) ? sb[tid - o] : 0;
        __syncthreads();
        sb[tid] = v + u;
        __syncthreads();
    }
    int excl = sb[tid] - sum;
    #pragma unroll
    for (int r = 0; r < 8; r++) {
        int i = base + r;
        g_segstart[i] = excl;
        g_segend[i]   = excl + c[r];
        g_cursor[i]   = excl;
        g_count[i]    = 0;           // reset for next graph replay
        excl += c[r];
    }
}

// ---------------- L3: scatter edges into segments (8 x 1024) -----------------
// Within-segment order is race-dependent, but k_nodesort canonicalizes it.
__global__ void k_scatter(const int* __restrict__ ei) {
    int t = blockIdx.x * blockDim.x + threadIdx.x;   // 0..8191
    int src = ei[t];
    int dst = ei[NEDGE + t];
    int pos = atomicAdd(&g_cursor[src], 1);
    g_ekeys[pos] = ((unsigned int)src << 13) | (unsigned int)dst;
}

// ---------------- L4: per-node segment sort + degree (8 x 1024) --------------
// Insertion sort per tiny segment (avg len 1) -> ascending dst, deterministic.
// deg = unique keys in segment.
__global__ void k_nodesort() {
    int i = blockIdx.x * blockDim.x + threadIdx.x;   // node id
    int s0 = g_segstart[i], s1 = g_segend[i];
    for (int a = s0 + 1; a < s1; a++) {
        unsigned int key = g_ekeys[a];
        int b = a - 1;
        while (b >= s0 && g_ekeys[b] > key) { g_ekeys[b + 1] = g_ekeys[b]; b--; }
        g_ekeys[b + 1] = key;
    }
    int deg = 0;
    unsigned int prev = 0xFFFFFFFFu;
    for (int a = s0; a < s1; a++) {
        unsigned int k2 = g_ekeys[a];
        if (k2 != prev) deg++;
        prev = k2;
    }
    g_deg[i] = deg;
}

// ---------------- L5: per-position weight term (warp per edge) ---------------
// Compensated f32 dot rounded once via double; term = (dis_i*sim)*dis_j.
// Duplicates (adjacent equal keys, same segment) -> exact +0.0f.
__global__ void k_term() {
    int p = (blockIdx.x * blockDim.x + threadIdx.x) >> 5;
    int lane = threadIdx.x & 31;
    unsigned int key = g_ekeys[p];
    if (p > 0 && g_ekeys[p - 1] == key) {            // duplicate (warp-uniform)
        if (lane == 0) g_term[p] = 0.0f;
        return;
    }
    int i = (int)(key >> 13);
    int j = (int)(key & 8191u);
    float4 a = ((const float4*)(g_xn + (size_t)i * DIMS))[lane];
    float4 b = ((const float4*)(g_xn + (size_t)j * DIMS))[lane];
    float s = 0.0f, c = 0.0f;
    acc_prod(a.x, b.x, s, c); acc_prod(a.y, b.y, s, c);
    acc_prod(a.z, b.z, s, c); acc_prod(a.w, b.w, s, c);
    #pragma unroll
    for (int o = 16; o; o >>= 1) {
        float s2 = __shfl_xor_sync(0xFFFFFFFFu, s, o);
        float c2 = __shfl_xor_sync(0xFFFFFFFFu, c, o);
        merge_sc(s2, c2, s, c);
    }
    if (lane == 0) {
        float sim = (float)((double)s + (double)c);
        int dj = g_deg[j];
        float disi = (float)(1.0 / sqrt((double)g_deg[i]));
        float disj = (dj > 0) ? (float)(1.0 / sqrt((double)dj)) : 0.0f;
        g_term[p] = (disi * sim) * disj;
    }
}

// ---- rank sort: R13-proven 4-block bitonic over u64 keys, weights fused -----
__global__ void kw_full() {
    __shared__ unsigned long long s[TILE];
    int t = threadIdx.x, base = blockIdx.x * TILE;
    for (int l = t; l < TILE; l += 1024) {
        int i = base + l;
        float acc = 0.0f;
        int s0 = g_segstart[i], s1 = g_segend[i];
        for (int p = s0; p < s1; p++) acc += g_term[p];   // ascending j
        g_w[i] = acc;
        unsigned int u = __float_as_uint(acc);
        u = (u & 0x80000000u) ? ~u : (u | 0x80000000u);   // monotone map
        s[l] = ~(((unsigned long long)u << 32) | (unsigned int)(N_NODES - 1 - i));
    }
    __syncthreads();
    for (int k = 2; k <= TILE; k <<= 1)
        for (int j = k >> 1; j > 0; j >>= 1) {
            int lo = t & (j - 1);
            int il = ((t & ~(j - 1)) << 1) | lo;
            int pr = il | j;
            bool up = (((base + il) & k) == 0);
            unsigned long long a = s[il], b = s[pr];
            if ((a > b) == up) { s[il] = b; s[pr] = a; }
            __syncthreads();
        }
    g_keys[base + t] = s[t]; g_keys[base + t + 1024] = s[t + 1024];
}
__global__ void kw_g(int k, int j) {
    int t = blockIdx.x * blockDim.x + threadIdx.x;   // 4096 threads
    int lo = t & (j - 1);
    int i = ((t & ~(j - 1)) << 1) | lo;
    int pr = i | j;
    bool up = ((i & k) == 0);
    unsigned long long a = g_keys[i], b = g_keys[pr];
    if ((a > b) == up) { g_keys[i] = b; g_keys[pr] = a; }
}
__global__ void kw_fin(int k) {
    __shared__ unsigned long long s[TILE];
    int t = threadIdx.x, base = blockIdx.x * TILE;
    s[t] = g_keys[base + t]; s[t + 1024] = g_keys[base + t + 1024];
    __syncthreads();
    for (int j = TILE >> 1; j > 0; j >>= 1) {
        int lo = t & (j - 1);
        int il = ((t & ~(j - 1)) << 1) | lo;
        int pr = il | j;
        bool up = (((base + il) & k) == 0);
        unsigned long long a = s[il], b = s[pr];
        if ((a > b) == up) { s[il] = b; s[pr] = a; }
        __syncthreads();
    }
    g_keys[base + t] = s[t]; g_keys[base + t + 1024] = s[t + 1024];
}

// perm / batch_pool / weights outputs + selection flags
__global__ void k_permout(const int* __restrict__ batch, float* __restrict__ out) {
    int k = blockIdx.x * blockDim.x + threadIdx.x;
    if (k >= KSEL) return;
    unsigned long long key = ~g_keys[k];             // undo inversion
    int idx = (N_NODES - 1) - (int)(unsigned int)(key & 0xFFFFFFFFu);
    g_perm[k] = idx;
    g_sel[idx] = 1;
    g_newid[idx] = k;
    out[OFF_PERM + k]  = (float)idx;
    out[OFF_BATCH + k] = (float)batch[idx];
    out[OFF_W + k]     = g_w[idx];
}

// x_pool gather
__global__ void k_xpool(const float* __restrict__ x, float* __restrict__ out) {
    int t = blockIdx.x * blockDim.x + threadIdx.x;
    if (t >= KSEL * DIMS) return;
    int k = t >> 7, d = t & 127;
    out[OFF_X + t] = x[(size_t)g_perm[k] * DIMS + d];
}

// keep = ascending unselected node indices; emit remapped edge endpoints.
__global__ void k_keep(const int* __restrict__ ei, float* __restrict__ out) {
    __shared__ int s_off[1024];
    int tid = threadIdx.x;
    int base = tid * 8;
    int c = 0;
    #pragma unroll
    for (int r = 0; r < 8; r++) c += (g_sel[base + r] == 0);
    s_off[tid] = c;
    __syncthreads();
    for (int o = 1; o < 1024; o <<= 1) {
        int v = s_off[tid];
        int u = (tid >= o) ? s_off[tid - o] : 0;
        __syncthreads();
        s_off[tid] = v + u;
        __syncthreads();
    }
    int off = s_off[tid] - c;   // exclusive prefix
    for (int r = 0; r < 8; r++) {
        int node = base + r;
        if (!g_sel[node]) {
            out[OFF_EI + off] = (float)g_newid[ei[node]];
            out[OFF_EJ + off] = (float)g_newid[ei[NEDGE + node]];
            off++;
        }
    }
}

// ---------------- launch ----------------
extern "C" void kernel_launch(void* const* d_in, const int* in_sizes, int n_in,
                              void* d_out, int out_size) {
    const float* x     = (const float*)d_in[0];
    const int*   ei    = (const int*)d_in[1];     // int32 (confirmed round 5)
    const int*   batch = (const int*)d_in[2];
    float* out = (float*)d_out;

    k_init    <<<256, 1024>>>(x, ei);     // norms + clears + edge histogram
    k_scan    <<<1, 1024>>>();            // offsets + cursors, re-zero histogram
    k_scatter <<<8, 1024>>>(ei);          // edges into per-src segments
    k_nodesort<<<8, 1024>>>();            // canonical ascending-dst order + deg
    k_term    <<<1024, 256>>>();          // warp per position

    kw_full   <<<4, 1024>>>();            // weights + rank keys + local sort
    kw_g      <<<16, 256>>>(4096, 2048);
    kw_fin    <<<4, 1024>>>(4096);
    kw_g      <<<16, 256>>>(8192, 4096);
    kw_g      <<<16, 256>>>(8192, 2048);
    kw_fin    <<<4, 1024>>>(8192);

    k_permout <<<16, 256>>>(batch, out);
    k_xpool   <<<2048, 256>>>(x, out);
    k_keep    <<<1, 1024>>>(ei, out);
}